// round 17
// baseline (speedup 1.0000x reference)
#include <cuda_runtime.h>
#include <cuda_bf16.h>
#include <math.h>
#include <stdint.h>

#define CCH   256
#define TT      4
#define HH     64
#define WWID   64
#define NWIN  128
#define MTOT  (NWIN*256)
#define ATT_SCALE 0.1767766952966369f
#define LOG2E     1.4426950408889634f

// -------- global scratch --------
__device__ __nv_bfloat16  g_xn_bf[MTOT * CCH];       // LN output (bf16)
__device__ __nv_bfloat16  g_q_bf [MTOT * CCH];       // q: scaled(*log2e), pair-permuted, bf16
__device__ __nv_bfloat16  g_k_bf [MTOT * CCH];       // k natural bf16
__device__ uint16_t       g_v_f16[MTOT * CCH];       // v natural f16
__device__ __nv_bfloat16  g_att_bf[MTOT * CCH];      // attention output (bf16)
__device__ __nv_bfloat16  g_wqkv_bf[768 * 256];
__device__ __nv_bfloat16  g_wproj_bf[256 * 256];

// pack (lo, hi) floats into bf16x2 word
__device__ __forceinline__ uint32_t pack_bf16x2(float lo, float hi) {
    uint32_t r;
    asm("cvt.rn.bf16x2.f32 %0, %1, %2;" : "=r"(r) : "f"(hi), "f"(lo));
    return r;
}

// pack (lo, hi) floats into f16x2 word
__device__ __forceinline__ uint32_t pack_f16x2(float lo, float hi) {
    uint32_t r;
    asm("cvt.rn.f16x2.f32 %0, %1, %2;" : "=r"(r) : "f"(hi), "f"(lo));
    return r;
}

// 2-way packed exp2 on f16x2
__device__ __forceinline__ uint32_t ex2_f16x2(uint32_t x) {
    uint32_t r;
    asm("ex2.approx.f16x2 %0, %1;" : "=r"(r) : "r"(x));
    return r;
}

__device__ __forceinline__ void mma_bf16(float* c,
                                         uint32_t a0, uint32_t a1, uint32_t a2, uint32_t a3,
                                         uint32_t b0, uint32_t b1) {
    asm volatile("mma.sync.aligned.m16n8k16.row.col.f32.bf16.bf16.f32 "
                 "{%0,%1,%2,%3}, {%4,%5,%6,%7}, {%8,%9}, {%0,%1,%2,%3};"
                 : "+f"(c[0]), "+f"(c[1]), "+f"(c[2]), "+f"(c[3])
                 : "r"(a0), "r"(a1), "r"(a2), "r"(a3), "r"(b0), "r"(b1));
}

__device__ __forceinline__ void mma_f16(float* c,
                                        uint32_t a0, uint32_t a1, uint32_t a2, uint32_t a3,
                                        uint32_t b0, uint32_t b1) {
    asm volatile("mma.sync.aligned.m16n8k16.row.col.f32.f16.f16.f32 "
                 "{%0,%1,%2,%3}, {%4,%5,%6,%7}, {%8,%9}, {%0,%1,%2,%3};"
                 : "+f"(c[0]), "+f"(c[1]), "+f"(c[2]), "+f"(c[3])
                 : "r"(a0), "r"(a1), "r"(a2), "r"(a3), "r"(b0), "r"(b1));
}

__device__ __forceinline__ void ldsm_x4(uint32_t& r0, uint32_t& r1, uint32_t& r2, uint32_t& r3,
                                        uint32_t addr) {
    asm volatile("ldmatrix.sync.aligned.m8n8.x4.shared.b16 {%0,%1,%2,%3}, [%4];"
                 : "=r"(r0), "=r"(r1), "=r"(r2), "=r"(r3) : "r"(addr));
}

__device__ __forceinline__ void ldsm_x4_trans(uint32_t& r0, uint32_t& r1, uint32_t& r2, uint32_t& r3,
                                              uint32_t addr) {
    asm volatile("ldmatrix.sync.aligned.m8n8.x4.trans.shared.b16 {%0,%1,%2,%3}, [%4];"
                 : "=r"(r0), "=r"(r1), "=r"(r2), "=r"(r3) : "r"(addr));
}

__device__ __forceinline__ void cpasync16(uint32_t dst, const void* src) {
    asm volatile("cp.async.ca.shared.global [%0], [%1], 16;\n" :: "r"(dst), "l"(src));
}
#define CP_COMMIT asm volatile("cp.async.commit_group;\n" ::: "memory")
#define CP_WAIT1  asm volatile("cp.async.wait_group 1;\n" ::: "memory")
#define CP_WAIT0  asm volatile("cp.async.wait_group 0;\n" ::: "memory")

// ============================================================
// Kernel 0: weight prep (fp32 -> bf16 copies)
// ============================================================
__global__ void prep_weights(const float* __restrict__ wq, const float* __restrict__ wp)
{
    int i = blockIdx.x * blockDim.x + threadIdx.x;
    if (i < 768 * 256)  g_wqkv_bf[i]  = __float2bfloat16_rn(wq[i]);
    if (i < 256 * 256)  g_wproj_bf[i] = __float2bfloat16_rn(wp[i]);
}

// ============================================================
// Kernel 1: coalesced gather + LayerNorm (bf16 xn only)
// ============================================================
__global__ __launch_bounds__(256) void ln_gather_kernel(const float* __restrict__ x,
                                                        const float* __restrict__ gamma,
                                                        const float* __restrict__ beta)
{
    __shared__ float tile[256][65];
    __shared__ float rsum[4][64], rsq[4][64];
    __shared__ float mus[64], rstds[64];

    int bx  = blockIdx.x;
    int bt  = bx >> 6;
    int h   = bx & 63;
    int tid = threadIdx.x;

    const float* slice = x + ((size_t)bt * 256) * 4096 + h * 64;

    int cl = tid >> 4;
    int w4 = (tid & 15) * 4;
    #pragma unroll
    for (int it = 0; it < 16; it++) {
        int c = it * 16 + cl;
        float4 v = *(const float4*)(slice + (size_t)c * 4096 + w4);
        tile[c][w4 + 0] = v.x; tile[c][w4 + 1] = v.y;
        tile[c][w4 + 2] = v.z; tile[c][w4 + 3] = v.w;
    }
    __syncthreads();

    {
        int w = tid & 63, part = tid >> 6;
        float s = 0.f, q = 0.f;
        #pragma unroll
        for (int i = 0; i < 64; i++) {
            float v = tile[part * 64 + i][w];
            s += v; q += v * v;
        }
        rsum[part][w] = s; rsq[part][w] = q;
    }
    __syncthreads();
    if (tid < 64) {
        float tot = rsum[0][tid] + rsum[1][tid] + rsum[2][tid] + rsum[3][tid];
        float tq  = rsq[0][tid]  + rsq[1][tid]  + rsq[2][tid]  + rsq[3][tid];
        float mu  = tot * (1.0f / 256.0f);
        float var = tq * (1.0f / 256.0f) - mu * mu;
        mus[tid]  = mu;
        rstds[tid] = rsqrtf(var + 1e-5f);
    }
    __syncthreads();

    int c = tid;
    float gm = gamma[c], be = beta[c];
    int b  = bt >> 2, t = bt & 3;
    int hi = h >> 3, r = h & 7;
    int nbase = b * 64 + hi * 8;
    int lbase = t * 64 + r * 8;
    #pragma unroll 8
    for (int w = 0; w < 64; w++) {
        int n = nbase + (w >> 3);
        int l = lbase + (w & 7);
        size_t m = (size_t)n * 256 + l;
        float val = tile[c][w];
        float xn  = (val - mus[w]) * rstds[w] * gm + be;
        g_xn_bf[m * 256 + c] = __float2bfloat16_rn(xn);
    }
}

// ============================================================
// legacy bf16 GEMM path (proj): 128x128, BK=32, 3-stage
// ============================================================
#define STAGE_BYTES (128 * 40 * 2)

__device__ __forceinline__ void stage_load_bf(uint32_t sA, uint32_t sB,
                                              const __nv_bfloat16* Ag,
                                              const __nv_bfloat16* Bg,
                                              int lrow, int lhalf, int kt)
{
    const __nv_bfloat16* a = Ag + (size_t)lrow * 256 + kt + lhalf * 16;
    const __nv_bfloat16* b = Bg + (size_t)lrow * 256 + kt + lhalf * 16;
    uint32_t da = sA + (lrow * 40 + lhalf * 16) * 2;
    uint32_t db = sB + (lrow * 40 + lhalf * 16) * 2;
    cpasync16(da,      a);
    cpasync16(da + 16, a + 8);
    cpasync16(db,      b);
    cpasync16(db + 16, b + 8);
}

__device__ __forceinline__ void gemm_bf16_main(float (*c)[4][4],
                                               const __nv_bfloat16* Ab,
                                               const __nv_bfloat16* Bb,
                                               uint32_t asb, uint32_t bsb)
{
    int tid  = threadIdx.x;
    int lane = tid & 31, warp = tid >> 5;
    int wm = (warp & 1) * 64;
    int wn = (warp >> 1) * 32;

    int lrow = tid >> 1, lhalf = tid & 1;

    int a_row = lane & 15;
    int a_col = (lane >> 4) * 8;
    int b_row = (lane & 7) + (lane >> 4) * 8;
    int b_col = ((lane >> 3) & 1) * 8;

    uint32_t aS[3] = { asb, asb + STAGE_BYTES, asb + 2 * STAGE_BYTES };
    uint32_t bS[3] = { bsb, bsb + STAGE_BYTES, bsb + 2 * STAGE_BYTES };

    stage_load_bf(aS[0], bS[0], Ab, Bb, lrow, lhalf, 0);
    CP_COMMIT;
    stage_load_bf(aS[1], bS[1], Ab, Bb, lrow, lhalf, 32);
    CP_COMMIT;

    #pragma unroll
    for (int it = 0; it < 8; it++) {
        if (it == 7) { CP_WAIT0; } else { CP_WAIT1; }
        __syncthreads();
        if (it < 6) {
            stage_load_bf(aS[(it+2)%3], bS[(it+2)%3], Ab, Bb, lrow, lhalf, (it+2)*32);
            CP_COMMIT;
        }
        int s = it % 3;
        #pragma unroll
        for (int ks = 0; ks < 2; ks++) {
            uint32_t af[4][4];
            #pragma unroll
            for (int mi = 0; mi < 4; mi++) {
                uint32_t addr = aS[s] + ((wm + mi*16 + a_row) * 40 + ks*16 + a_col) * 2;
                ldsm_x4(af[mi][0], af[mi][1], af[mi][2], af[mi][3], addr);
            }
            uint32_t bf[4][2];
            {
                uint32_t addr0 = bS[s] + ((wn +  0 + b_row) * 40 + ks*16 + b_col) * 2;
                uint32_t addr1 = bS[s] + ((wn + 16 + b_row) * 40 + ks*16 + b_col) * 2;
                ldsm_x4(bf[0][0], bf[0][1], bf[1][0], bf[1][1], addr0);
                ldsm_x4(bf[2][0], bf[2][1], bf[3][0], bf[3][1], addr1);
            }
            #pragma unroll
            for (int mi = 0; mi < 4; mi++)
                #pragma unroll
                for (int j = 0; j < 4; j++)
                    mma_bf16(c[mi][j], af[mi][0], af[mi][1], af[mi][2], af[mi][3],
                             bf[j][0], bf[j][1]);
        }
    }
    __syncthreads();
}

// ============================================================
// Kernel 2: QKV GEMM, wide-N: 512 threads, block tile 128x256,
// grid (3,256) -> blockIdx.x selects q / k / v exactly.
// A read 3x instead of 6x. 16 warps (4m x 4n), warp tile 32x64.
// ============================================================
#define ASTG (128 * 40 * 2)    // 10240 B per A stage
#define BSTG (256 * 40 * 2)    // 20480 B per B stage

__global__ __launch_bounds__(512, 1) void gemm_qkv_wide(const float* __restrict__ bias)
{
    __shared__ __align__(16) __nv_bfloat16 As[3][128][40];
    __shared__ __align__(16) __nv_bfloat16 Bs[3][256][40];

    int tid  = threadIdx.x;
    int lane = tid & 31, warp = tid >> 5;
    int g = lane >> 2, t = lane & 3;
    int wm = (warp & 3) * 32;
    int wn = (warp >> 2) * 64;

    const __nv_bfloat16* Ab = g_xn_bf   + (size_t)blockIdx.y * 128 * 256;
    const __nv_bfloat16* Bb = g_wqkv_bf + (size_t)blockIdx.x * 256 * 256;

    uint32_t asb = (uint32_t)__cvta_generic_to_shared(&As[0][0][0]);
    uint32_t bsb = (uint32_t)__cvta_generic_to_shared(&Bs[0][0][0]);
    uint32_t aS[3] = { asb, asb + ASTG, asb + 2 * ASTG };
    uint32_t bS[3] = { bsb, bsb + BSTG, bsb + 2 * BSTG };

    // loaders: A one 16B chunk/thread; B two 16B chunks/thread
    int arow = tid >> 2, aunit = tid & 3;
    int b0row = (2*tid) >> 2,   b0unit = (2*tid) & 3;
    int b1row = (2*tid+1) >> 2, b1unit = (2*tid+1) & 3;

    #define QLOAD(st, kt) do {                                                      \
        cpasync16(aS[st] + (arow * 40 + aunit * 8) * 2,                             \
                  Ab + (size_t)arow * 256 + (kt) + aunit * 8);                      \
        cpasync16(bS[st] + (b0row * 40 + b0unit * 8) * 2,                           \
                  Bb + (size_t)b0row * 256 + (kt) + b0unit * 8);                    \
        cpasync16(bS[st] + (b1row * 40 + b1unit * 8) * 2,                           \
                  Bb + (size_t)b1row * 256 + (kt) + b1unit * 8);                    \
        CP_COMMIT;                                                                  \
    } while (0)

    int a_row = lane & 15;
    int a_col = (lane >> 4) * 8;
    int b_row = (lane & 7) + (lane >> 4) * 8;
    int b_col = ((lane >> 3) & 1) * 8;

    float c[2][8][4] = {};

    QLOAD(0, 0);
    QLOAD(1, 32);

    #pragma unroll
    for (int it = 0; it < 8; it++) {
        if (it == 7) { CP_WAIT0; } else { CP_WAIT1; }
        __syncthreads();
        if (it < 6) QLOAD((it+2)%3, (it+2)*32);
        int s = it % 3;
        #pragma unroll
        for (int ks = 0; ks < 2; ks++) {
            uint32_t af[2][4];
            #pragma unroll
            for (int mi = 0; mi < 2; mi++) {
                uint32_t addr = aS[s] + ((wm + mi*16 + a_row) * 40 + ks*16 + a_col) * 2;
                ldsm_x4(af[mi][0], af[mi][1], af[mi][2], af[mi][3], addr);
            }
            uint32_t bf[8][2];
            #pragma unroll
            for (int q = 0; q < 4; q++) {
                uint32_t addr = bS[s] + ((wn + 16*q + b_row) * 40 + ks*16 + b_col) * 2;
                ldsm_x4(bf[2*q][0], bf[2*q][1], bf[2*q+1][0], bf[2*q+1][1], addr);
            }
            #pragma unroll
            for (int mi = 0; mi < 2; mi++)
                #pragma unroll
                for (int j = 0; j < 8; j++)
                    mma_bf16(c[mi][j], af[mi][0], af[mi][1], af[mi][2], af[mi][3],
                             bf[j][0], bf[j][1]);
        }
    }
    #undef QLOAD

    // ---- epilogue: blockIdx.x = 0 -> q, 1 -> k, 2 -> v ----
    int mbase = blockIdx.y * 128 + wm;
    const float* bia = bias + blockIdx.x * 256;

    if (blockIdx.x == 0) {                // q: scale + pair-permute (bf16)
        const float sc = ATT_SCALE * LOG2E;
        uint32_t* qout = (uint32_t*)g_q_bf;
        #pragma unroll
        for (int mi = 0; mi < 2; mi++) {
            int row0 = mbase + mi*16 + g;
            #pragma unroll
            for (int j = 0; j < 8; j++) {
                int col  = wn + j*8 + 2*t;          // 0..255
                float2 bv = *(const float2*)&bia[col];
                int head = col >> 5;
                int word = t*4 + (j & 3);
                qout[(size_t)row0       * 128 + head*16 + word] =
                    pack_bf16x2((c[mi][j][0] + bv.x) * sc, (c[mi][j][1] + bv.y) * sc);
                qout[(size_t)(row0 + 8) * 128 + head*16 + word] =
                    pack_bf16x2((c[mi][j][2] + bv.x) * sc, (c[mi][j][3] + bv.y) * sc);
            }
        }
    } else if (blockIdx.x == 1) {         // k: natural bf16
        uint32_t* outp = (uint32_t*)g_k_bf;
        #pragma unroll
        for (int mi = 0; mi < 2; mi++) {
            int row0 = mbase + mi*16 + g;
            #pragma unroll
            for (int j = 0; j < 8; j++) {
                int col = wn + j*8 + 2*t;
                float2 bv = *(const float2*)&bia[col];
                outp[(size_t)row0       * 128 + (col >> 1)] =
                    pack_bf16x2(c[mi][j][0] + bv.x, c[mi][j][1] + bv.y);
                outp[(size_t)(row0 + 8) * 128 + (col >> 1)] =
                    pack_bf16x2(c[mi][j][2] + bv.x, c[mi][j][3] + bv.y);
            }
        }
    } else {                              // v: natural f16
        uint32_t* outp = (uint32_t*)g_v_f16;
        #pragma unroll
        for (int mi = 0; mi < 2; mi++) {
            int row0 = mbase + mi*16 + g;
            #pragma unroll
            for (int j = 0; j < 8; j++) {
                int col = wn + j*8 + 2*t;
                float2 bv = *(const float2*)&bia[col];
                outp[(size_t)row0       * 128 + (col >> 1)] =
                    pack_f16x2(c[mi][j][0] + bv.x, c[mi][j][1] + bv.y);
                outp[(size_t)(row0 + 8) * 128 + (col >> 1)] =
                    pack_f16x2(c[mi][j][2] + bv.x, c[mi][j][3] + bv.y);
            }
        }
    }
}

// ============================================================
// Kernel 3: attention (unchanged from R15)
// ============================================================
__global__ __launch_bounds__(256, 2) void attn_mma()
{
    __shared__ __align__(16) __nv_bfloat16 Ks[256 * 40];
    __shared__ __align__(16) uint16_t      Vs[256 * 40];

    int win  = blockIdx.x >> 3;
    int head = blockIdx.x & 7;
    int tid  = threadIdx.x;
    int lane = tid & 31, warp = tid >> 5;
    int g = lane >> 2, t = lane & 3;

    const __nv_bfloat16* baseK = g_k_bf  + (size_t)win * 256 * 256 + head * 32;
    const uint16_t*      baseV = g_v_f16 + (size_t)win * 256 * 256 + head * 32;
    const uint32_t* qwords = (const uint32_t*)g_q_bf + (size_t)win * 256 * 128 + head * 16;
    uint32_t* obase = (uint32_t*)g_att_bf + (size_t)win * 256 * 128;

    uint32_t ks_base = (uint32_t)__cvta_generic_to_shared(Ks);
    uint32_t vs_base = (uint32_t)__cvta_generic_to_shared(Vs);

    {
        int key = tid;
        uint32_t dk = ks_base + key * 80;
        uint32_t dv = vs_base + key * 80;
        const __nv_bfloat16* sk = baseK + (size_t)key * 256;
        const uint16_t*      sv = baseV + (size_t)key * 256;
        cpasync16(dk,      sk);      cpasync16(dk + 16, sk + 8);
        cpasync16(dk + 32, sk + 16); cpasync16(dk + 48, sk + 24);
        cpasync16(dv,      sv);      cpasync16(dv + 16, sv + 8);
        cpasync16(dv + 32, sv + 16); cpasync16(dv + 48, sv + 24);
    }
    CP_COMMIT;

    int mrow = warp * 32;
    uint32_t Qw[4][4];
    #pragma unroll
    for (int rg = 0; rg < 4; rg++) {
        int row = mrow + rg * 8 + g;
        *(uint4*)&Qw[rg][0] = *(const uint4*)(qwords + (size_t)row * 128 + t * 4);
    }

    CP_WAIT0;
    __syncthreads();

    int bk_row = (lane & 7) + (lane >> 4) * 8;
    int bk_col = ((lane >> 3) & 1) * 8;
    uint32_t koff_lane = ks_base + bk_row * 80 + bk_col * 2;
    int mat = lane >> 3;
    uint32_t voff_lane = vs_base + ((mat & 1) * 8 + (lane & 7)) * 80 + (mat >> 1) * 16;

    const uint32_t F16_ONES = 0x3C003C00u;

    float rsf[2][4] = {};
    float co[2][4][4] = {};

    #pragma unroll
    for (int ch = 0; ch < 8; ch++) {
        int kb = ch * 32;

        float sf[2][4][4] = {};
        #pragma unroll
        for (int kh = 0; kh < 2; kh++) {
            uint32_t kf[4][2];
            ldsm_x4(kf[0][0], kf[0][1], kf[1][0], kf[1][1],
                    koff_lane + (kb     ) * 80 + kh * 32);
            ldsm_x4(kf[2][0], kf[2][1], kf[3][0], kf[3][1],
                    koff_lane + (kb + 16) * 80 + kh * 32);
            #pragma unroll
            for (int ta = 0; ta < 2; ta++) {
                uint32_t a0 = Qw[2*ta    ][2*kh    ];
                uint32_t a1 = Qw[2*ta + 1][2*kh    ];
                uint32_t a2 = Qw[2*ta    ][2*kh + 1];
                uint32_t a3 = Qw[2*ta + 1][2*kh + 1];
                #pragma unroll
                for (int nf = 0; nf < 4; nf++)
                    mma_bf16(sf[ta][nf], a0, a1, a2, a3, kf[nf][0], kf[nf][1]);
            }
        }

        uint32_t pf[2][4][2];
        #pragma unroll
        for (int ta = 0; ta < 2; ta++)
            #pragma unroll
            for (int nf = 0; nf < 4; nf++) {
                pf[ta][nf][0] = ex2_f16x2(pack_f16x2(sf[ta][nf][0], sf[ta][nf][1]));
                pf[ta][nf][1] = ex2_f16x2(pack_f16x2(sf[ta][nf][2], sf[ta][nf][3]));
            }

        #pragma unroll
        for (int kc = 0; kc < 2; kc++) {
            uint32_t vaddr = voff_lane + (kb + kc * 16) * 80;
            uint32_t b0, b1, b2, b3, b4, b5, b6, b7;
            ldsm_x4_trans(b0, b1, b2, b3, vaddr);
            ldsm_x4_trans(b4, b5, b6, b7, vaddr + 32);
            #pragma unroll
            for (int ta = 0; ta < 2; ta++) {
                uint32_t pa0 = pf[ta][2*kc  ][0];
                uint32_t pa1 = pf[ta][2*kc  ][1];
                uint32_t pa2 = pf[ta][2*kc+1][0];
                uint32_t pa3 = pf[ta][2*kc+1][1];
                mma_f16(co[ta][0], pa0, pa1, pa2, pa3, b0, b1);
                mma_f16(co[ta][1], pa0, pa1, pa2, pa3, b2, b3);
                mma_f16(co[ta][2], pa0, pa1, pa2, pa3, b4, b5);
                mma_f16(co[ta][3], pa0, pa1, pa2, pa3, b6, b7);
                mma_f16(rsf[ta],   pa0, pa1, pa2, pa3, F16_ONES, F16_ONES);
            }
        }
    }

    #pragma unroll
    for (int ta = 0; ta < 2; ta++) {
        float inv0 = 1.0f / rsf[ta][0];
        float inv1 = 1.0f / rsf[ta][2];

        int mr = mrow + ta * 16;
        #pragma unroll
        for (int nf = 0; nf < 4; nf++) {
            int col = head * 32 + nf*8 + 2*t;
            obase[((size_t)(mr + g    ) * 256 + col) >> 1] =
                pack_bf16x2(co[ta][nf][0] * inv0, co[ta][nf][1] * inv0);
            obase[((size_t)(mr + g + 8) * 256 + col) >> 1] =
                pack_bf16x2(co[ta][nf][2] * inv1, co[ta][nf][3] * inv1);
        }
    }
}

// ============================================================
// Kernel 4: proj GEMM (bf16) + bias + residual(from x) + scatter
// ============================================================
__global__ __launch_bounds__(256, 2) void gemm_proj_bf16(const float* __restrict__ bias,
                                                         const float* __restrict__ x,
                                                         float* __restrict__ out)
{
    __shared__ __align__(16) char smem_raw[128 * 130 * 4];
    __nv_bfloat16* As0 = (__nv_bfloat16*)smem_raw;
    __nv_bfloat16* Bs0 = (__nv_bfloat16*)(smem_raw + 3 * STAGE_BYTES);
    float (*Cs)[130]   = (float (*)[130])smem_raw;

    int tid  = threadIdx.x;
    int lane = tid & 31, warp = tid >> 5;
    int g = lane >> 2, t = lane & 3;
    int wm = (warp & 1) * 64;
    int wn = (warp >> 1) * 32;

    const __nv_bfloat16* Ab = g_att_bf   + (size_t)blockIdx.y * 128 * 256;
    const __nv_bfloat16* Bb = g_wproj_bf + (size_t)blockIdx.x * 128 * 256;

    uint32_t asb = (uint32_t)__cvta_generic_to_shared(As0);
    uint32_t bsb = (uint32_t)__cvta_generic_to_shared(Bs0);

    float c[4][4][4] = {};
    gemm_bf16_main(c, Ab, Bb, asb, bsb);

    int nbase = blockIdx.x * 128;
    #pragma unroll
    for (int m = 0; m < 4; m++) {
        int rl = wm + m*16 + g;
        #pragma unroll
        for (int j = 0; j < 4; j++) {
            int cl = wn + j*8 + 2*t;
            float2 bv = *(const float2*)&bias[nbase + cl];
            *(float2*)&Cs[rl    ][cl] = make_float2(c[m][j][0] + bv.x, c[m][j][1] + bv.y);
            *(float2*)&Cs[rl + 8][cl] = make_float2(c[m][j][2] + bv.x, c[m][j][3] + bv.y);
        }
    }
    __syncthreads();

    int by   = blockIdx.y;
    int n    = by >> 1;
    int half = by & 1;
    int b  = n >> 6, hi = (n >> 3) & 7, wi = n & 7;

    int cc  = tid & 127;
    int trh = tid >> 7;
    #pragma unroll
    for (int tr2 = 0; tr2 < 8; tr2++) {
        int tr = tr2 * 2 + trh;
        int t2 = tr >> 3, r = tr & 7;
        int l0 = t2 * 64 + r * 8;
        int t_full = half * 2 + t2;
        int bt = b * 4 + t_full;
        int h  = hi * 8 + r;
        int col = nbase + cc;
        size_t oaddr = (((size_t)bt * 256 + col) * 64 + h) * 64 + wi * 8;
        #pragma unroll
        for (int j = 0; j < 2; j++) {
            float4 xr = *(const float4*)&x[oaddr + 4*j];
            float4 v;
            v.x = Cs[l0 + 4*j + 0][cc] + xr.x;
            v.y = Cs[l0 + 4*j + 1][cc] + xr.y;
            v.z = Cs[l0 + 4*j + 2][cc] + xr.z;
            v.w = Cs[l0 + 4*j + 3][cc] + xr.w;
            *(float4*)&out[oaddr + 4*j] = v;
        }
    }
}

// ============================================================
extern "C" void kernel_launch(void* const* d_in, const int* in_sizes, int n_in,
                              void* d_out, int out_size)
{
    const float* x      = (const float*)d_in[0];
    const float* w_qkv  = (const float*)d_in[1];
    const float* b_qkv  = (const float*)d_in[2];
    const float* w_proj = (const float*)d_in[3];
    const float* b_proj = (const float*)d_in[4];
    const float* gamma  = (const float*)d_in[5];
    const float* beta   = (const float*)d_in[6];
    float* out = (float*)d_out;

    prep_weights<<<768, 256>>>(w_qkv, w_proj);
    ln_gather_kernel<<<512, 256>>>(x, gamma, beta);
    gemm_qkv_wide<<<dim3(3, 256), 512>>>(b_qkv);
    attn_mma<<<NWIN * 8, 256>>>();
    gemm_proj_bf16<<<dim3(2, 256), 256>>>(b_proj, x, out);
}